// round 15
// baseline (speedup 1.0000x reference)
#include <cuda_runtime.h>
#include <cuda_fp16.h>
#include <cstdint>
#include <math.h>

#define S1 0.07905694150420948f   // 1/sqrt(160)
#define S2 0.07216878364870323f   // 1/sqrt(192)
#define SQRT2F 1.41421356237309515f
#define NCHUNKS 16384             // 524288 px / 32 per warp-chunk
#define GRID_MAIN 608             // 4 CTAs/SM x 152 SMs
#define TPB 128
#define NWARPS_TOTAL (GRID_MAIN * (TPB / 32))

// ---- weight fragment layout (u32 indices inside g_wfrag / smem) ----
// per frag-slot: ((ntile*KT + kt)*32 + lane)*2 + reg
#define F1_OFF 0        // [8 ntile][2 kt][32 lane][2 reg] = 1024 u32
#define F2_OFF 1024     // [8][4][32][2] = 2048 u32
#define F3_OFF 3072
#define F4_OFF 5120     // [1][4][32][2] = 256 u32
#define WFRAG_U32 5376

// ---- bias-broadcast region (floats inside g_znew / smem) ----
// layers 1-3: slot(l,b,n,c) = ((l*8+b)*8+n)*4+c, each slot = float4 {z0,z1,z0,z1}
#define ZB4_F   3072    // 3*8*8*4*4
#define Z4B_F   128     // 8 batches x 4 c-slots x float4
#define ZNEW_F  3208    // + fw[8]
#define FW_F    3200

// ---- shared memory byte offsets ----
#define SW_BASE   0               // weight frags: 21504 B
#define SM_ZB4    21504           // 12288 B (layers 1-3 bias broadcast)
#define SM_Z4B    33792           // 512 B
#define SM_FW     34304           // 32 B
#define SM_EH     34336           // 128 rows x 17 u32 = 8704 B
#define SM_TOTAL  43040

// ---- device globals (prep outputs) ----
__device__ __align__(16) uint32_t g_wfrag[WFRAG_U32];
__device__ __align__(16) float    g_znew[ZNEW_F];

// ---------------- helpers ----------------
__device__ __forceinline__ void mma16816(float* c, const uint32_t* a, const uint32_t* b) {
    asm volatile(
        "mma.sync.aligned.m16n8k16.row.col.f32.f16.f16.f32 "
        "{%0,%1,%2,%3}, {%4,%5,%6,%7}, {%8,%9}, {%0,%1,%2,%3};"
        : "+f"(c[0]), "+f"(c[1]), "+f"(c[2]), "+f"(c[3])
        : "r"(a[0]), "r"(a[1]), "r"(a[2]), "r"(a[3]), "r"(b[0]), "r"(b[1]));
}

__device__ __forceinline__ void lds128f(float* d, uint32_t addr) {
    asm volatile("ld.shared.v4.f32 {%0,%1,%2,%3}, [%4];"
        : "=f"(d[0]), "=f"(d[1]), "=f"(d[2]), "=f"(d[3]) : "r"(addr));
}

// pack two fp32 -> fp16x2 word (low half = v0)
__device__ __forceinline__ uint32_t packh2(float v0, float v1) {
    __half2 h = __floats2half2_rn(v0, v1);
    return *(uint32_t*)&h;
}

// lrelu (sqrt2 folded into next layer's weights): max(t, 0.2t) in half2
__device__ __forceinline__ uint32_t act2(uint32_t w, __half2 k02) {
    __half2 t = *(__half2*)&w;
    __half2 r = __hmax2(t, __hmul2(t, k02));
    return *(uint32_t*)&r;
}

// ---------------- prep kernel ----------------
__global__ void prep_kernel(const float* __restrict__ c, const float* __restrict__ fu,
                            const float* __restrict__ w1, const float* __restrict__ b1,
                            const float* __restrict__ w2, const float* __restrict__ b2,
                            const float* __restrict__ w3, const float* __restrict__ b3,
                            const float* __restrict__ w4, const float* __restrict__ b4)
{
    const int t = blockIdx.x * blockDim.x + threadIdx.x;
    const int stride = gridDim.x * blockDim.x;
    const int warp = t >> 5;
    const int lane = t & 31;

    // freq weights
    if (t < 8) {
        float lim = (float)(t + 1) / 9.0f;
        float w = (fu[0] - lim) * 9.0f;
        g_znew[FW_F + t] = fminf(fmaxf(w, 0.0f), 1.0f);
    }
    // zero z4 padding slots (c = 2,3 for every batch)
    if (t < Z4B_F && ((t >> 2) & 3) >= 2) g_znew[ZB4_F + t] = 0.0f;

    // per-batch cond biases via warp reductions: warp w -> (b, j); broadcast-write
    if (warp < 512) {
        const int b = warp >> 6, j = warp & 63;
        const float* cb = c + b * 128;
        float a1 = 0.f, a2 = 0.f, a3 = 0.f;
#pragma unroll
        for (int q = 0; q < 4; q++) {
            int k = lane + q * 32;
            float cv = cb[k];
            a1 = fmaf(cv, __ldg(w1 + j * 160 + 32 + k), a1);
            a2 = fmaf(cv, __ldg(w2 + j * 192 + 64 + k), a2);
            a3 = fmaf(cv, __ldg(w3 + j * 192 + 64 + k), a3);
        }
#pragma unroll
        for (int off = 16; off; off >>= 1) {
            a1 += __shfl_xor_sync(0xffffffffu, a1, off);
            a2 += __shfl_xor_sync(0xffffffffu, a2, off);
            a3 += __shfl_xor_sync(0xffffffffu, a3, off);
        }
        if (lane == 0) {
            const int n = j >> 3, cc = (j >> 1) & 3, e = j & 1;
            float zv[3];
            zv[0] = b1[j] + S1 * a1;
            zv[1] = b2[j] + S2 * a2;
            zv[2] = b3[j] + S2 * a3;
#pragma unroll
            for (int l = 0; l < 3; l++) {
                int slot = ((l * 8 + b) * 8 + n) * 4 + cc;
                g_znew[slot * 4 + e]     = zv[l];
                g_znew[slot * 4 + e + 2] = zv[l];
            }
        }
    }
    // z4: 32 warps -> (b, j) with j<4; broadcast-write into c-slots 0..1
    if (warp < 32) {
        const int b = warp >> 2, j = warp & 3;
        const float* cb = c + b * 128;
        float a4 = 0.f;
#pragma unroll
        for (int q = 0; q < 4; q++) {
            int k = lane + q * 32;
            a4 = fmaf(cb[k], __ldg(w4 + j * 192 + 64 + k), a4);
        }
#pragma unroll
        for (int off = 16; off; off >>= 1) a4 += __shfl_xor_sync(0xffffffffu, a4, off);
        if (lane == 0) {
            float v = b4[j] + S2 * a4;
            const int cc = j >> 1, e = j & 1;
            int slot = b * 4 + cc;
            g_znew[ZB4_F + slot * 4 + e]     = v;
            g_znew[ZB4_F + slot * 4 + e + 2] = v;
        }
    }

    // weight fragments (5376 fp16x2 slots); sqrt2 folded into layers 2-4
    for (int s = t; s < 5376; s += stride) {
        int layer, rel, Foff, KT;
        if (s < 1024)      { layer = 1; rel = s;        Foff = F1_OFF; KT = 2; }
        else if (s < 3072) { layer = 2; rel = s - 1024; Foff = F2_OFF; KT = 4; }
        else if (s < 5120) { layer = 3; rel = s - 3072; Foff = F3_OFF; KT = 4; }
        else               { layer = 4; rel = s - 5120; Foff = F4_OFF; KT = 4; }
        int reg  = rel & 1;
        int ln   = (rel >> 1) & 31;
        int tk   = (rel >> 6) % KT;
        int nt   = (rel >> 6) / KT;
        int gg = ln >> 2, cc = ln & 3;
        int n = nt * 8 + gg;
        int k0 = tk * 16 + 2 * cc + (reg ? 8 : 0);
        const float S2F = S2 * SQRT2F;
        float v0, v1;
        if (layer == 1)      { v0 = w1[n * 160 + k0] * S1;  v1 = w1[n * 160 + k0 + 1] * S1; }
        else if (layer == 2) { v0 = w2[n * 192 + k0] * S2F; v1 = w2[n * 192 + k0 + 1] * S2F; }
        else if (layer == 3) { v0 = w3[n * 192 + k0] * S2F; v1 = w3[n * 192 + k0 + 1] * S2F; }
        else { v0 = (n < 4) ? w4[n * 192 + k0] * S2F : 0.0f;
               v1 = (n < 4) ? w4[n * 192 + k0 + 1] * S2F : 0.0f; }
        g_wfrag[Foff + rel] = packh2(v0, v1);
    }
}

// ---------------- one 64-wide layer (LDS.128 bias init; kt-outer MMA; 2-op act) ----
template<int KT>
__device__ __forceinline__ void layer(uint32_t Ah[2][4][4], const char* wf,
                                      uint32_t zaddr, int lane, __half2 k02)
{
    float C[2][8][4];
#pragma unroll
    for (int n = 0; n < 8; n++) {
        lds128f(C[0][n], zaddr + n * 64);
        lds128f(C[1][n], zaddr + n * 64);
        uint2 b[KT];
#pragma unroll
        for (int kt = 0; kt < KT; kt++)
            b[kt] = *(const uint2*)(wf + ((n * KT + kt) * 32 + lane) * 8);
#pragma unroll
        for (int kt = 0; kt < KT; kt++) {
            mma16816(C[0][n], Ah[0][kt], (const uint32_t*)&b[kt]);
            mma16816(C[1][n], Ah[1][kt], (const uint32_t*)&b[kt]);
        }
    }
#pragma unroll
    for (int n = 0; n < 8; n++) {
        const int kd = n >> 1, rd = (n & 1) * 2;
#pragma unroll
        for (int m = 0; m < 2; m++) {
            Ah[m][kd][rd + 0] = act2(packh2(C[m][n][0], C[m][n][1]), k02);
            Ah[m][kd][rd + 1] = act2(packh2(C[m][n][2], C[m][n][3]), k02);
        }
    }
}

// ---------------- embedding compute+store for one chunk (returns mask) ----------
__device__ __forceinline__ float emb_store(float2 xy, const float* s_fw, uint32_t* ehr)
{
    float sx, cx, sy, cy;
    __sincosf(xy.x * 0.1f, &sx, &cx);
    __sincosf(xy.y * 0.1f, &sy, &cy);
    float r = sqrtf(fmaf(xy.x, xy.x, xy.y * xy.y));
    float u = fmaxf(r - 1.0f, 0.0f);
    float maskv = __fdividef(2.0f, __expf(2.0f * u) + 1.0f);

#pragma unroll
    for (int i = 0; i < 8; i++) {
        float w = s_fw[i];
        ehr[2 * i + 0] = packh2(sx * w, sy * w);
        ehr[2 * i + 1] = packh2(cx * w, cy * w);
        if (i < 7) {
            float nsx = 2.0f * sx * cx;
            float ncx = fmaf(-2.0f * sx, sx, 1.0f);
            float nsy = 2.0f * sy * cy;
            float ncy = fmaf(-2.0f * sy, sy, 1.0f);
            sx = nsx; cx = ncx; sy = nsy; cy = ncy;
        }
    }
    return maskv;
}

// ---------------- main kernel ----------------
__global__ __launch_bounds__(TPB, 4) void decoder_kernel(const float* __restrict__ coords,
                                                         float* __restrict__ out)
{
    extern __shared__ __align__(16) char sm[];
    const int tid = threadIdx.x;
    const int wid = tid >> 5;
    const int lane = tid & 31;
    const int g = lane >> 2, c = lane & 3;

    const __half2 k02 = __float2half2_rn(0.2f);

    // ---- stage weights + biases into shared (once per CTA) ----
    {
        const uint4* src = (const uint4*)g_wfrag;
        uint4* dst = (uint4*)(sm + SW_BASE);
        for (int i = tid; i < WFRAG_U32 / 4; i += TPB) dst[i] = src[i];
        const float4* zs = (const float4*)g_znew;
        float4* zd = (float4*)(sm + SM_ZB4);
        for (int i = tid; i < ZNEW_F / 4; i += TPB) zd[i] = zs[i];
    }
    __syncthreads();

    // ---- per-CTA phase stagger (co-resident warps on one SMSP = same wid across
    // the 4 CTAs of this SM). Step ~2600 cyc = chunk/4: 650 dependent FMAs. ----
    {
        int iters = (blockIdx.x & 3) * 650;
        float dly = (float)(lane + 1);
        for (int i = 0; i < iters; i++) dly = fmaf(dly, 1.0000001f, 0.0001f);
        if (dly < 0.0f) ((volatile float*)sm)[0] = dly;   // never true; keeps chain alive
    }

    const uint32_t smb = (uint32_t)__cvta_generic_to_shared(sm);
    const float* s_fw = (const float*)(sm + SM_FW);
    uint32_t* s_eh = (uint32_t*)(sm + SM_EH);
    uint32_t* ehr = s_eh + (wid * 32 + lane) * 17;   // this lane's embedding row
    const float2* coords2 = (const float2*)coords;

    // ---- prologue: embedding for first chunk ----
    int chunk = blockIdx.x * 4 + wid;
    float2 xy = coords2[chunk * 32 + lane];
    float maskv_nxt = emb_store(xy, s_fw, ehr);

    for (; chunk < NCHUNKS; chunk += NWARPS_TOTAL) {
        const int pixbase = chunk * 32;
        const int batch = chunk >> 11;
        const float maskv = maskv_nxt;

        __syncwarp();   // embedding rows for this chunk visible across lanes

        // ---- load layer-1 A fragments from smem ----
        uint32_t Ah[2][4][4];
#pragma unroll
        for (int m = 0; m < 2; m++) {
            const int r0 = wid * 32 + m * 16 + g;
            const uint32_t* eh0 = s_eh + r0 * 17;
            const uint32_t* eh1 = eh0 + 8 * 17;
#pragma unroll
            for (int kt = 0; kt < 2; kt++) {
                Ah[m][kt][0] = eh0[kt * 8 + c];
                Ah[m][kt][1] = eh1[kt * 8 + c];
                Ah[m][kt][2] = eh0[kt * 8 + c + 4];
                Ah[m][kt][3] = eh1[kt * 8 + c + 4];
            }
        }
        __syncwarp();   // all lanes done reading old embedding before overwrite

        // ---- prefetch next chunk's coords (LDG latency hidden by layers 1-2) ----
        {
            int nc = chunk + NWARPS_TOTAL;
            int pc = (nc < NCHUNKS) ? nc : chunk;
            xy = coords2[pc * 32 + lane];
        }

        // bias-broadcast base for this batch (+ c slot)
        const uint32_t zbb = smb + SM_ZB4 + (uint32_t)batch * 512 + (uint32_t)c * 16;
        layer<2>(Ah, sm + F1_OFF * 4, zbb,            lane, k02);
        layer<4>(Ah, sm + F2_OFF * 4, zbb + 8 * 512,  lane, k02);

        // ---- pipelined: compute + store NEXT chunk's embedding in the MMA shadow ----
        maskv_nxt = emb_store(xy, s_fw, ehr);

        layer<4>(Ah, sm + F3_OFF * 4, zbb + 16 * 512, lane, k02);

        // ---- layer 4: single n8 tile (cols 0..3 real) ----
        float C40[4], C41[4];
        {
            uint32_t z4a = smb + SM_Z4B + (uint32_t)batch * 64 + (uint32_t)c * 16;
            lds128f(C40, z4a);
            lds128f(C41, z4a);
        }
#pragma unroll
        for (int kt = 0; kt < 4; kt++) {
            uint2 bh = *(const uint2*)(sm + F4_OFF * 4 + (kt * 32 + lane) * 8);
            mma16816(C40, Ah[0][kt], (const uint32_t*)&bh);
            mma16816(C41, Ah[1][kt], (const uint32_t*)&bh);
        }

        // ---- masks via shfl (all lanes participate) ----
        float mk[2][2];
#pragma unroll
        for (int m = 0; m < 2; m++) {
            mk[m][0] = __shfl_sync(0xffffffffu, maskv, m * 16 + g);
            mk[m][1] = __shfl_sync(0xffffffffu, maskv, m * 16 + 8 + g);
        }

        // ---- output: threads c<2 hold real cols (2c, 2c+1) ----
        if (c < 2) {
            float2 o0, o1;
            o0.x = C40[0] * mk[0][0];
            o0.y = C40[1] * mk[0][0];
            o1.x = C40[2] * mk[0][1];
            o1.y = C40[3] * mk[0][1];
            *(float2*)(out + (pixbase + g) * 4 + 2 * c) = o0;
            *(float2*)(out + (pixbase + 8 + g) * 4 + 2 * c) = o1;
            o0.x = C41[0] * mk[1][0];
            o0.y = C41[1] * mk[1][0];
            o1.x = C41[2] * mk[1][1];
            o1.y = C41[3] * mk[1][1];
            *(float2*)(out + (pixbase + 16 + g) * 4 + 2 * c) = o0;
            *(float2*)(out + (pixbase + 24 + g) * 4 + 2 * c) = o1;
        }
    }
}

// ---------------- launch ----------------
extern "C" void kernel_launch(void* const* d_in, const int* in_sizes, int n_in,
                              void* d_out, int out_size)
{
    const float* coords = (const float*)d_in[0];
    const float* c      = (const float*)d_in[1];
    const float* fu     = (const float*)d_in[2];
    const float* w1     = (const float*)d_in[3];
    const float* b1     = (const float*)d_in[4];
    const float* w2     = (const float*)d_in[5];
    const float* b2     = (const float*)d_in[6];
    const float* w3     = (const float*)d_in[7];
    const float* b3     = (const float*)d_in[8];
    const float* w4     = (const float*)d_in[9];
    const float* b4     = (const float*)d_in[10];
    float* out = (float*)d_out;

    cudaFuncSetAttribute(decoder_kernel, cudaFuncAttributeMaxDynamicSharedMemorySize, SM_TOTAL);
    prep_kernel<<<64, 256>>>(c, fu, w1, b1, w2, b2, w3, b3, w4, b4);
    decoder_kernel<<<GRID_MAIN, TPB, SM_TOTAL>>>(coords, out);
}

// round 16
// speedup vs baseline: 1.1623x; 1.1623x over previous
#include <cuda_runtime.h>
#include <cuda_fp16.h>
#include <cstdint>
#include <math.h>

#define S1 0.07905694150420948f   // 1/sqrt(160)
#define S2 0.07216878364870323f   // 1/sqrt(192)
#define SQRT2F 1.41421356237309515f
#define NCHUNKS 16384             // 524288 px / 32 per warp-chunk
#define GRID_MAIN 608             // 4 CTAs/SM x 152 SMs
#define TPB 128
#define NWARPS_TOTAL (GRID_MAIN * (TPB / 32))

// ---- weight fragment layout (u32 indices inside g_wfrag / smem) ----
// per frag-slot: ((ntile*KT + kt)*32 + lane)*2 + reg
#define F1_OFF 0        // [8 ntile][2 kt][32 lane][2 reg] = 1024 u32
#define F2_OFF 1024     // [8][4][32][2] = 2048 u32
#define F3_OFF 3072
#define F4_OFF 5120     // [1][4][32][2] = 256 u32
#define WFRAG_U32 5376

// ---- bias-broadcast region (floats inside g_znew / smem) ----
// layers 1-3: slot(l,b,n,c) = ((l*8+b)*8+n)*4+c, each slot = float4 {z0,z1,z0,z1}
#define ZB4_F   3072    // 3*8*8*4*4
#define Z4B_F   128     // 8 batches x 4 c-slots x float4
#define ZNEW_F  3208    // + fw[8]
#define FW_F    3200

// ---- shared memory byte offsets ----
#define SW_BASE   0               // weight frags: 21504 B
#define SM_ZB4    21504           // 12288 B (layers 1-3 bias broadcast)
#define SM_Z4B    33792           // 512 B
#define SM_FW     34304           // 32 B
#define SM_EH     34336           // 128 rows x 17 u32 = 8704 B
#define SM_TOTAL  43040

// ---- device globals (prep outputs) ----
__device__ __align__(16) uint32_t g_wfrag[WFRAG_U32];
__device__ __align__(16) float    g_znew[ZNEW_F];

// ---------------- helpers ----------------
__device__ __forceinline__ void mma16816(float* c, const uint32_t* a, const uint32_t* b) {
    asm volatile(
        "mma.sync.aligned.m16n8k16.row.col.f32.f16.f16.f32 "
        "{%0,%1,%2,%3}, {%4,%5,%6,%7}, {%8,%9}, {%0,%1,%2,%3};"
        : "+f"(c[0]), "+f"(c[1]), "+f"(c[2]), "+f"(c[3])
        : "r"(a[0]), "r"(a[1]), "r"(a[2]), "r"(a[3]), "r"(b[0]), "r"(b[1]));
}

__device__ __forceinline__ void lds128f(float* d, uint32_t addr) {
    asm volatile("ld.shared.v4.f32 {%0,%1,%2,%3}, [%4];"
        : "=f"(d[0]), "=f"(d[1]), "=f"(d[2]), "=f"(d[3]) : "r"(addr));
}

// pack two fp32 -> fp16x2 word (low half = v0)
__device__ __forceinline__ uint32_t packh2(float v0, float v1) {
    __half2 h = __floats2half2_rn(v0, v1);
    return *(uint32_t*)&h;
}

// lrelu (sqrt2 folded into next layer's weights): max(t, 0.2t) in half2
__device__ __forceinline__ uint32_t act2(uint32_t w, __half2 k02) {
    __half2 t = *(__half2*)&w;
    __half2 r = __hmax2(t, __hmul2(t, k02));
    return *(uint32_t*)&r;
}

// ---------------- prep kernel ----------------
__global__ void prep_kernel(const float* __restrict__ c, const float* __restrict__ fu,
                            const float* __restrict__ w1, const float* __restrict__ b1,
                            const float* __restrict__ w2, const float* __restrict__ b2,
                            const float* __restrict__ w3, const float* __restrict__ b3,
                            const float* __restrict__ w4, const float* __restrict__ b4)
{
    const int t = blockIdx.x * blockDim.x + threadIdx.x;
    const int stride = gridDim.x * blockDim.x;
    const int warp = t >> 5;
    const int lane = t & 31;

    // freq weights
    if (t < 8) {
        float lim = (float)(t + 1) / 9.0f;
        float w = (fu[0] - lim) * 9.0f;
        g_znew[FW_F + t] = fminf(fmaxf(w, 0.0f), 1.0f);
    }
    // zero z4 padding slots (c = 2,3 for every batch)
    if (t < Z4B_F && ((t >> 2) & 3) >= 2) g_znew[ZB4_F + t] = 0.0f;

    // per-batch cond biases via warp reductions: warp w -> (b, j); broadcast-write
    if (warp < 512) {
        const int b = warp >> 6, j = warp & 63;
        const float* cb = c + b * 128;
        float a1 = 0.f, a2 = 0.f, a3 = 0.f;
#pragma unroll
        for (int q = 0; q < 4; q++) {
            int k = lane + q * 32;
            float cv = cb[k];
            a1 = fmaf(cv, __ldg(w1 + j * 160 + 32 + k), a1);
            a2 = fmaf(cv, __ldg(w2 + j * 192 + 64 + k), a2);
            a3 = fmaf(cv, __ldg(w3 + j * 192 + 64 + k), a3);
        }
#pragma unroll
        for (int off = 16; off; off >>= 1) {
            a1 += __shfl_xor_sync(0xffffffffu, a1, off);
            a2 += __shfl_xor_sync(0xffffffffu, a2, off);
            a3 += __shfl_xor_sync(0xffffffffu, a3, off);
        }
        if (lane == 0) {
            const int n = j >> 3, cc = (j >> 1) & 3, e = j & 1;
            float zv[3];
            zv[0] = b1[j] + S1 * a1;
            zv[1] = b2[j] + S2 * a2;
            zv[2] = b3[j] + S2 * a3;
#pragma unroll
            for (int l = 0; l < 3; l++) {
                int slot = ((l * 8 + b) * 8 + n) * 4 + cc;
                g_znew[slot * 4 + e]     = zv[l];
                g_znew[slot * 4 + e + 2] = zv[l];
            }
        }
    }
    // z4: 32 warps -> (b, j) with j<4; broadcast-write into c-slots 0..1
    if (warp < 32) {
        const int b = warp >> 2, j = warp & 3;
        const float* cb = c + b * 128;
        float a4 = 0.f;
#pragma unroll
        for (int q = 0; q < 4; q++) {
            int k = lane + q * 32;
            a4 = fmaf(cb[k], __ldg(w4 + j * 192 + 64 + k), a4);
        }
#pragma unroll
        for (int off = 16; off; off >>= 1) a4 += __shfl_xor_sync(0xffffffffu, a4, off);
        if (lane == 0) {
            float v = b4[j] + S2 * a4;
            const int cc = j >> 1, e = j & 1;
            int slot = b * 4 + cc;
            g_znew[ZB4_F + slot * 4 + e]     = v;
            g_znew[ZB4_F + slot * 4 + e + 2] = v;
        }
    }

    // weight fragments (5376 fp16x2 slots); sqrt2 folded into layers 2-4
    for (int s = t; s < 5376; s += stride) {
        int layer, rel, Foff, KT;
        if (s < 1024)      { layer = 1; rel = s;        Foff = F1_OFF; KT = 2; }
        else if (s < 3072) { layer = 2; rel = s - 1024; Foff = F2_OFF; KT = 4; }
        else if (s < 5120) { layer = 3; rel = s - 3072; Foff = F3_OFF; KT = 4; }
        else               { layer = 4; rel = s - 5120; Foff = F4_OFF; KT = 4; }
        int reg  = rel & 1;
        int ln   = (rel >> 1) & 31;
        int tk   = (rel >> 6) % KT;
        int nt   = (rel >> 6) / KT;
        int gg = ln >> 2, cc = ln & 3;
        int n = nt * 8 + gg;
        int k0 = tk * 16 + 2 * cc + (reg ? 8 : 0);
        const float S2F = S2 * SQRT2F;
        float v0, v1;
        if (layer == 1)      { v0 = w1[n * 160 + k0] * S1;  v1 = w1[n * 160 + k0 + 1] * S1; }
        else if (layer == 2) { v0 = w2[n * 192 + k0] * S2F; v1 = w2[n * 192 + k0 + 1] * S2F; }
        else if (layer == 3) { v0 = w3[n * 192 + k0] * S2F; v1 = w3[n * 192 + k0 + 1] * S2F; }
        else { v0 = (n < 4) ? w4[n * 192 + k0] * S2F : 0.0f;
               v1 = (n < 4) ? w4[n * 192 + k0 + 1] * S2F : 0.0f; }
        g_wfrag[Foff + rel] = packh2(v0, v1);
    }
}

// ---------------- one 64-wide layer: paired n-tiles, 4 accumulator chains ----
template<int KT>
__device__ __forceinline__ void layer(uint32_t Ah[2][4][4], const char* wf,
                                      uint32_t zaddr, int lane, __half2 k02)
{
    float C[2][8][4];
#pragma unroll
    for (int np = 0; np < 4; np++) {
        const int n0 = 2 * np, n1 = 2 * np + 1;
        lds128f(C[0][n0], zaddr + n0 * 64);
        lds128f(C[1][n0], zaddr + n0 * 64);
        lds128f(C[0][n1], zaddr + n1 * 64);
        lds128f(C[1][n1], zaddr + n1 * 64);
        uint2 b0[KT], b1[KT];
#pragma unroll
        for (int kt = 0; kt < KT; kt++) {
            b0[kt] = *(const uint2*)(wf + ((n0 * KT + kt) * 32 + lane) * 8);
            b1[kt] = *(const uint2*)(wf + ((n1 * KT + kt) * 32 + lane) * 8);
        }
#pragma unroll
        for (int kt = 0; kt < KT; kt++) {
            mma16816(C[0][n0], Ah[0][kt], (const uint32_t*)&b0[kt]);
            mma16816(C[1][n0], Ah[1][kt], (const uint32_t*)&b0[kt]);
            mma16816(C[0][n1], Ah[0][kt], (const uint32_t*)&b1[kt]);
            mma16816(C[1][n1], Ah[1][kt], (const uint32_t*)&b1[kt]);
        }
    }
#pragma unroll
    for (int n = 0; n < 8; n++) {
        const int kd = n >> 1, rd = (n & 1) * 2;
#pragma unroll
        for (int m = 0; m < 2; m++) {
            Ah[m][kd][rd + 0] = act2(packh2(C[m][n][0], C[m][n][1]), k02);
            Ah[m][kd][rd + 1] = act2(packh2(C[m][n][2], C[m][n][3]), k02);
        }
    }
}

// ---------------- embedding compute+store for one chunk (returns mask) ----------
__device__ __forceinline__ float emb_store(float2 xy, const float* s_fw, uint32_t* ehr)
{
    float sx, cx, sy, cy;
    __sincosf(xy.x * 0.1f, &sx, &cx);
    __sincosf(xy.y * 0.1f, &sy, &cy);
    float r = sqrtf(fmaf(xy.x, xy.x, xy.y * xy.y));
    float u = fmaxf(r - 1.0f, 0.0f);
    float maskv = __fdividef(2.0f, __expf(2.0f * u) + 1.0f);

#pragma unroll
    for (int i = 0; i < 8; i++) {
        float w = s_fw[i];
        ehr[2 * i + 0] = packh2(sx * w, sy * w);
        ehr[2 * i + 1] = packh2(cx * w, cy * w);
        if (i < 7) {
            float nsx = 2.0f * sx * cx;
            float ncx = fmaf(-2.0f * sx, sx, 1.0f);
            float nsy = 2.0f * sy * cy;
            float ncy = fmaf(-2.0f * sy, sy, 1.0f);
            sx = nsx; cx = ncx; sy = nsy; cy = ncy;
        }
    }
    return maskv;
}

// ---------------- main kernel ----------------
__global__ __launch_bounds__(TPB, 4) void decoder_kernel(const float* __restrict__ coords,
                                                         float* __restrict__ out)
{
    extern __shared__ __align__(16) char sm[];
    const int tid = threadIdx.x;
    const int wid = tid >> 5;
    const int lane = tid & 31;
    const int g = lane >> 2, c = lane & 3;

    const __half2 k02 = __float2half2_rn(0.2f);

    // ---- stage weights + biases into shared (once per CTA) ----
    {
        const uint4* src = (const uint4*)g_wfrag;
        uint4* dst = (uint4*)(sm + SW_BASE);
        for (int i = tid; i < WFRAG_U32 / 4; i += TPB) dst[i] = src[i];
        const float4* zs = (const float4*)g_znew;
        float4* zd = (float4*)(sm + SM_ZB4);
        for (int i = tid; i < ZNEW_F / 4; i += TPB) zd[i] = zs[i];
    }
    __syncthreads();

    const uint32_t smb = (uint32_t)__cvta_generic_to_shared(sm);
    const float* s_fw = (const float*)(sm + SM_FW);
    uint32_t* s_eh = (uint32_t*)(sm + SM_EH);
    uint32_t* ehr = s_eh + (wid * 32 + lane) * 17;   // this lane's embedding row
    const float2* coords2 = (const float2*)coords;

    // ---- prologue: embedding for first chunk ----
    int chunk = blockIdx.x * 4 + wid;
    float2 xy = coords2[chunk * 32 + lane];
    float maskv_nxt = emb_store(xy, s_fw, ehr);

    for (; chunk < NCHUNKS; chunk += NWARPS_TOTAL) {
        const int pixbase = chunk * 32;
        const int batch = chunk >> 11;
        const float maskv = maskv_nxt;

        __syncwarp();   // embedding rows for this chunk visible across lanes

        // ---- load layer-1 A fragments from smem ----
        uint32_t Ah[2][4][4];
#pragma unroll
        for (int m = 0; m < 2; m++) {
            const int r0 = wid * 32 + m * 16 + g;
            const uint32_t* eh0 = s_eh + r0 * 17;
            const uint32_t* eh1 = eh0 + 8 * 17;
#pragma unroll
            for (int kt = 0; kt < 2; kt++) {
                Ah[m][kt][0] = eh0[kt * 8 + c];
                Ah[m][kt][1] = eh1[kt * 8 + c];
                Ah[m][kt][2] = eh0[kt * 8 + c + 4];
                Ah[m][kt][3] = eh1[kt * 8 + c + 4];
            }
        }
        __syncwarp();   // all lanes done reading old embedding before overwrite

        // ---- prefetch next chunk's coords (LDG latency hidden by layers 1-2) ----
        {
            int nc = chunk + NWARPS_TOTAL;
            int pc = (nc < NCHUNKS) ? nc : chunk;
            xy = coords2[pc * 32 + lane];
        }

        // bias-broadcast base for this batch (+ c slot)
        const uint32_t zbb = smb + SM_ZB4 + (uint32_t)batch * 512 + (uint32_t)c * 16;
        layer<2>(Ah, sm + F1_OFF * 4, zbb,            lane, k02);
        layer<4>(Ah, sm + F2_OFF * 4, zbb + 8 * 512,  lane, k02);

        // ---- pipelined: compute + store NEXT chunk's embedding in the MMA shadow ----
        maskv_nxt = emb_store(xy, s_fw, ehr);

        layer<4>(Ah, sm + F3_OFF * 4, zbb + 16 * 512, lane, k02);

        // ---- layer 4: single n8 tile (cols 0..3 real) ----
        float C40[4], C41[4];
        {
            uint32_t z4a = smb + SM_Z4B + (uint32_t)batch * 64 + (uint32_t)c * 16;
            lds128f(C40, z4a);
            lds128f(C41, z4a);
        }
#pragma unroll
        for (int kt = 0; kt < 4; kt++) {
            uint2 bh = *(const uint2*)(sm + F4_OFF * 4 + (kt * 32 + lane) * 8);
            mma16816(C40, Ah[0][kt], (const uint32_t*)&bh);
            mma16816(C41, Ah[1][kt], (const uint32_t*)&bh);
        }

        // ---- masks via shfl (all lanes participate) ----
        float mk[2][2];
#pragma unroll
        for (int m = 0; m < 2; m++) {
            mk[m][0] = __shfl_sync(0xffffffffu, maskv, m * 16 + g);
            mk[m][1] = __shfl_sync(0xffffffffu, maskv, m * 16 + 8 + g);
        }

        // ---- output: threads c<2 hold real cols (2c, 2c+1) ----
        if (c < 2) {
            float2 o0, o1;
            o0.x = C40[0] * mk[0][0];
            o0.y = C40[1] * mk[0][0];
            o1.x = C40[2] * mk[0][1];
            o1.y = C40[3] * mk[0][1];
            *(float2*)(out + (pixbase + g) * 4 + 2 * c) = o0;
            *(float2*)(out + (pixbase + 8 + g) * 4 + 2 * c) = o1;
            o0.x = C41[0] * mk[1][0];
            o0.y = C41[1] * mk[1][0];
            o1.x = C41[2] * mk[1][1];
            o1.y = C41[3] * mk[1][1];
            *(float2*)(out + (pixbase + 16 + g) * 4 + 2 * c) = o0;
            *(float2*)(out + (pixbase + 24 + g) * 4 + 2 * c) = o1;
        }
    }
}

// ---------------- launch ----------------
extern "C" void kernel_launch(void* const* d_in, const int* in_sizes, int n_in,
                              void* d_out, int out_size)
{
    const float* coords = (const float*)d_in[0];
    const float* c      = (const float*)d_in[1];
    const float* fu     = (const float*)d_in[2];
    const float* w1     = (const float*)d_in[3];
    const float* b1     = (const float*)d_in[4];
    const float* w2     = (const float*)d_in[5];
    const float* b2     = (const float*)d_in[6];
    const float* w3     = (const float*)d_in[7];
    const float* b3     = (const float*)d_in[8];
    const float* w4     = (const float*)d_in[9];
    const float* b4     = (const float*)d_in[10];
    float* out = (float*)d_out;

    cudaFuncSetAttribute(decoder_kernel, cudaFuncAttributeMaxDynamicSharedMemorySize, SM_TOTAL);
    prep_kernel<<<64, 256>>>(c, fu, w1, b1, w2, b2, w3, b3, w4, b4);
    decoder_kernel<<<GRID_MAIN, TPB, SM_TOTAL>>>(coords, out);
}